// round 1
// baseline (speedup 1.0000x reference)
#include <cuda_runtime.h>

#define T      1024
#define RS     16
#define NE     4
#define LRC    0.01f
#define GAMMAC 0.999f
#define PAD    96

// Scratch (device globals — no allocation allowed)
__device__ float g_err[NE];
__device__ float g_cw[RS * T];
__device__ float g_part[4][T * NE];

// ---------------------------------------------------------------------------
// Kernel A: error[e] = Dis[e, T-1] - sum_{rs,n} Fx[rs,e,n] * w0[rs,n]
// grid = NE blocks (one per e), 256 threads
// ---------------------------------------------------------------------------
__global__ void k_err(const float* __restrict__ Fx, const float* __restrict__ Dis,
                      const float* __restrict__ w0) {
    const int e = blockIdx.x;
    float acc = 0.f;
    for (int j = threadIdx.x; j < RS * T; j += 256) {
        const int rs = j >> 10;
        const int n  = j & (T - 1);
        acc += Fx[(((rs << 2) + e) << 10) + n] * w0[j];
    }
#pragma unroll
    for (int o = 16; o; o >>= 1) acc += __shfl_xor_sync(0xffffffffu, acc, o);
    __shared__ float s[8];
    const int lane = threadIdx.x & 31, w = threadIdx.x >> 5;
    if (lane == 0) s[w] = acc;
    __syncthreads();
    if (threadIdx.x == 0) {
        float t = 0.f;
#pragma unroll
        for (int i = 0; i < 8; i++) t += s[i];
        g_err[e] = Dis[e * T + (T - 1)] - t;
    }
}

// ---------------------------------------------------------------------------
// Kernel B: cw[rs,n] = w0[rs,n] + LR * sum_e Fx[rs,e,n] * err[e]
// grid = 64 blocks x 256 threads (16384 elements)
// ---------------------------------------------------------------------------
__global__ void k_cw(const float* __restrict__ Fx, const float* __restrict__ w0) {
    const int j  = blockIdx.x * 256 + threadIdx.x;
    const int rs = j >> 10, n = j & (T - 1);
    const float* f = Fx + (rs << 12) + n;   // Fx[rs, e, n], e-stride = 1024
    const float v = f[0]    * g_err[0] + f[1024] * g_err[1]
                  + f[2048] * g_err[2] + f[3072] * g_err[3];
    g_cw[j] = w0[j] + LRC * v;
}

// ---------------------------------------------------------------------------
// Kernel C: causal correlation partials
//   part[c][t,e] = sum_{rs in chunk c} sum_{n<=t} Fx[rs,e,t-n] * cw[rs,n]
// grid = (16 t-tiles of 64, NE, 4 rs-chunks), 256 threads.
// Thread (tg, st): tg = tid>>4 owns t = t0 + 4*tg + {0..3};
//                  st = tid&15 owns contiguous n-segment [st*seg, st*seg+seg).
// Zero front-pad of sF makes the n > t boundary implicit (reads 0).
// seg forced odd -> conflict-free strided smem access across st.
// ---------------------------------------------------------------------------
__global__ void k_conv(const float* __restrict__ Fx) {
    const int t0  = blockIdx.x << 6;      // t-tile base
    const int e   = blockIdx.y;
    const int c   = blockIdx.z;           // rs chunk (4 rs each)
    const int tid = threadIdx.x;
    const int tg  = tid >> 4;             // 0..15
    const int st  = tid & 15;             // 0..15

    const int L    = t0 + 64;             // n in [0, L)
    int seg        = (L >> 4) | 1;        // force odd (L divisible by 16)
    const int NEXT = seg << 4;            // padded segment span, <= L + 16

    __shared__ float sF[4][PAD + T];      // front zero-padded Fx rows
    __shared__ float sW[4][T + 32];       // tail zero-padded cw rows
    __shared__ float sRed[64][17];

#pragma unroll
    for (int q = 0; q < 4; q++) {
        const int rs = (c << 2) + q;
        const float* F = Fx + (((rs << 2) + e) << 10);
        for (int i = tid; i < PAD + L; i += 256)
            sF[q][i] = (i < PAD) ? 0.f : F[i - PAD];
        for (int i = tid; i < NEXT; i += 256)
            sW[q][i] = (i < L) ? g_cw[(rs << 10) + i] : 0.f;
    }
    __syncthreads();

    const int tb = t0 + (tg << 2);
    const int nb = st * seg;
    float a0 = 0.f, a1 = 0.f, a2 = 0.f, a3 = 0.f;

#pragma unroll
    for (int q = 0; q < 4; q++) {
        const float* F = &sF[q][PAD + tb];   // F[j - n] = Fx[.., tb+j-n]
        const float* W = sW[q];
        // sliding window f[j] = F[j - n]
        float f0 = F[0 - nb], f1 = F[1 - nb], f2 = F[2 - nb], f3 = F[3 - nb];
#pragma unroll 4
        for (int n = nb; n < nb + seg; n++) {
            const float w = W[n];
            a0 += f0 * w; a1 += f1 * w; a2 += f2 * w; a3 += f3 * w;
            f3 = f2; f2 = f1; f1 = f0; f0 = F[-1 - n];
        }
    }

    sRed[(tg << 2) + 0][st] = a0;
    sRed[(tg << 2) + 1][st] = a1;
    sRed[(tg << 2) + 2][st] = a2;
    sRed[(tg << 2) + 3][st] = a3;
    __syncthreads();

    if (tid < 64) {
        float s = 0.f;
#pragma unroll
        for (int k = 0; k < 16; k++) s += sRed[tid][k];
        g_part[c][((t0 + tid) << 2) + e] = s;
    }
}

// ---------------------------------------------------------------------------
// Kernel D: out[0:4096) = sum of 4 partials; out[4096:5120) = gamma vector
// ---------------------------------------------------------------------------
__global__ void k_final(float* __restrict__ out, int out_size) {
    const int i = blockIdx.x * 256 + threadIdx.x;
    if (i < T * NE) {
        if (i < out_size)
            out[i] = g_part[0][i] + g_part[1][i] + g_part[2][i] + g_part[3][i];
    } else if (i < T * NE + T) {
        if (i < out_size) {
            const int t = i - T * NE;
            out[i] = powf(GAMMAC, (float)(T - 1 - t));
        }
    }
}

// ---------------------------------------------------------------------------
extern "C" void kernel_launch(void* const* d_in, const int* in_sizes, int n_in,
                              void* d_out, int out_size) {
    const float* Fx  = (const float*)d_in[0];   // [4,4,4,1024]
    const float* Dis = (const float*)d_in[1];   // [4,1024]
    const float* w0  = (const float*)d_in[2];   // [4,4,1024]
    float* out = (float*)d_out;

    k_err<<<NE, 256>>>(Fx, Dis, w0);
    k_cw<<<64, 256>>>(Fx, w0);
    k_conv<<<dim3(16, NE, 4), 256>>>(Fx);
    k_final<<<(T * NE + T + 255) / 256, 256>>>(out, out_size);
}

// round 2
// speedup vs baseline: 1.2318x; 1.2318x over previous
#include <cuda_runtime.h>
#include <math.h>

#define T      1024
#define LRC    0.01f

// Scratch (device globals — allocation is forbidden)
__device__ float g_cw[16 * T];      // control weights [rs, n]
__device__ float g_epart[32];       // 8 cluster ranks x 4 e partials

// ---------------------------------------------------------------------------
// k1 (8-CTA cluster, 256 thr/CTA): fused err + cw.
//   err[e] = Dis[e,1023] - sum_{rs,n} Fx[rs,e,n]*w0[rs,n]
//   cw[rs,n] = w0[rs,n] + LR * sum_e Fx[rs,e,n]*err[e]
// Each CTA handles 2048 of the 16384 (rs,n) elements; partial err exchanged
// through global memory across a cluster barrier (release/acquire).
// ---------------------------------------------------------------------------
__global__ void __cluster_dims__(8, 1, 1) k1(const float* __restrict__ Fx,
                                             const float* __restrict__ Dis,
                                             const float* __restrict__ w0) {
    const int tid  = threadIdx.x;
    const int rank = blockIdx.x;              // grid == one cluster of 8
    const float4* w4  = (const float4*)w0;
    const float4* fx4 = (const float4*)Fx;

    // ---- phase A: partial err dot products over this CTA's slice ----
    float acc[4] = {0.f, 0.f, 0.f, 0.f};
#pragma unroll
    for (int s = 0; s < 2; s++) {
        const int i4 = rank * 512 + s * 256 + tid;    // float4 index into w0
        const float4 w = w4[i4];
        const int rs = i4 >> 8, n4 = i4 & 255;
#pragma unroll
        for (int e = 0; e < 4; e++) {
            const float4 x = fx4[(rs << 10) + (e << 8) + n4];
            acc[e] += x.x * w.x + x.y * w.y + x.z * w.z + x.w * w.w;
        }
    }
#pragma unroll
    for (int o = 16; o; o >>= 1)
#pragma unroll
        for (int e = 0; e < 4; e++) acc[e] += __shfl_xor_sync(0xffffffffu, acc[e], o);

    __shared__ float sp[8][4];
    __shared__ float serr[4];
    if ((tid & 31) == 0)
#pragma unroll
        for (int e = 0; e < 4; e++) sp[tid >> 5][e] = acc[e];
    __syncthreads();
    if (tid < 4) {
        float s = 0.f;
#pragma unroll
        for (int wq = 0; wq < 8; wq++) s += sp[wq][tid];
        g_epart[rank * 4 + tid] = s;
    }

    // cluster barrier: release partials, acquire peers' partials
    asm volatile("barrier.cluster.arrive.release.aligned;" ::: "memory");
    asm volatile("barrier.cluster.wait.acquire.aligned;"   ::: "memory");

    if (tid < 4) {
        volatile const float* gp = g_epart;
        float s = 0.f;
#pragma unroll
        for (int r = 0; r < 8; r++) s += gp[r * 4 + tid];
        serr[tid] = Dis[tid * T + (T - 1)] - s;
    }
    __syncthreads();
    const float e0 = serr[0], e1 = serr[1], e2 = serr[2], e3 = serr[3];

    // ---- phase B: cw over the same slice (Fx/w0 L1-hot from phase A) ----
    float4* cw4 = (float4*)g_cw;
#pragma unroll
    for (int s = 0; s < 2; s++) {
        const int i4 = rank * 512 + s * 256 + tid;
        float4 c = w4[i4];
        const int rs = i4 >> 8, n4 = i4 & 255;
        const float4 x0 = fx4[(rs << 10) + (0 << 8) + n4];
        const float4 x1 = fx4[(rs << 10) + (1 << 8) + n4];
        const float4 x2 = fx4[(rs << 10) + (2 << 8) + n4];
        const float4 x3 = fx4[(rs << 10) + (3 << 8) + n4];
        c.x += LRC * (x0.x * e0 + x1.x * e1 + x2.x * e2 + x3.x * e3);
        c.y += LRC * (x0.y * e0 + x1.y * e1 + x2.y * e2 + x3.y * e3);
        c.z += LRC * (x0.z * e0 + x1.z * e1 + x2.z * e2 + x3.z * e3);
        c.w += LRC * (x0.w * e0 + x1.w * e1 + x2.w * e2 + x3.w * e3);
        cw4[i4] = c;
    }
}

// ---------------------------------------------------------------------------
// k2: causal correlation + output + gamma, one launch.
//   out[t,e] = sum_{rs} sum_{n<=t} Fx[rs,e,t-n] * cw[rs,n]
// grid (32 pair-blocks, 4 e), 320 threads.
// Block b handles t-tiles b and 63-b (16 t's each): combined n-work
// LA + LB = 1040 for every b -> perfectly balanced grid.
// Thread = one 4-wide n-chunk of one tile; holds w[4] and all 16 t
// accumulators; t-loop is compile-time unrolled (no window-shift MOVs).
// 4 passes of 4 rs keep static smem under 48 KB; reduction overlays it.
// ---------------------------------------------------------------------------
#define PADF 20   // zero front-pad (5 float4) for the causal boundary

__global__ void __launch_bounds__(320, 1) k2(const float* __restrict__ Fx,
                                             float* __restrict__ out) {
    __shared__ __align__(16) union {
        struct { float sF[4][PADF + T + 4]; float sW[4][T]; } p;   // 33,152 B
        struct { float A[16][128]; float B[16][256]; } r;          // 24,576 B
    } u;
    __shared__ float s2[32][8];

    const int tid = threadIdx.x;
    const int b = blockIdx.x, e = blockIdx.y;
    const int t0A = b << 4, t0B = (63 - b) << 4;
    const int cA = (t0A + 16) >> 2;          // 4..128 chunks for tile A
    const int cB = 260 - cA;                  // chunks for tile B
    const bool active = tid < 260;
    const bool isA = tid < cA;
    const int t0 = isA ? t0A : t0B;
    const int nb = (isA ? tid : (tid - cA)) << 2;   // n-chunk base
    const int ab = 16 + t0 - nb;                     // aligned sF read base

    float acc[16];
#pragma unroll
    for (int j = 0; j < 16; j++) acc[j] = 0.f;

    const float4 z4 = make_float4(0.f, 0.f, 0.f, 0.f);

    for (int p = 0; p < 4; p++) {
        __syncthreads();
        // stage 4 rs rows of Fx (front zero-padded) and cw
#pragma unroll
        for (int qq = 0; qq < 4; qq++) {
            const int rs = (p << 2) + qq;
            const float4* src = (const float4*)(Fx + (((rs << 2) + e) << 10));
            float4* dF = (float4*)(u.p.sF[qq]);
            for (int i = tid; i < 261; i += 320) dF[i] = (i < 5) ? z4 : src[i - 5];
            const float4* ws = (const float4*)(g_cw + (rs << 10));
            float4* dW = (float4*)(u.p.sW[qq]);
            for (int i = tid; i < 256; i += 320) dW[i] = ws[i];
        }
        __syncthreads();

        if (active) {
#pragma unroll
            for (int qq = 0; qq < 4; qq++) {
                const float4 w = *(const float4*)&u.p.sW[qq][nb];
                const float4* F4 = (const float4*)&u.p.sF[qq][ab];
                float ff[24];
#pragma unroll
                for (int m = 0; m < 6; m++) {
                    const float4 v = F4[m];
                    ff[4 * m + 0] = v.x; ff[4 * m + 1] = v.y;
                    ff[4 * m + 2] = v.z; ff[4 * m + 3] = v.w;
                }
#pragma unroll
                for (int j = 0; j < 16; j++)
                    acc[j] += ff[4 + j] * w.x + ff[3 + j] * w.y
                            + ff[2 + j] * w.z + ff[1 + j] * w.w;
            }
        }
    }
    __syncthreads();

    // write per-chunk partials (overlays the pass buffers)
    if (active) {
        if (isA) {
#pragma unroll
            for (int j = 0; j < 16; j++) u.r.A[j][tid] = acc[j];
        } else {
#pragma unroll
            for (int j = 0; j < 16; j++) u.r.B[j][tid - cA] = acc[j];
        }
    }
    __syncthreads();

    // stage-1 reduction: 8 partials per (tile,t) row
    if (tid < 256) {
        const int row = tid >> 3, k = tid & 7;
        float s = 0.f;
        if (row < 16) {
            for (int c = k; c < cA; c += 8) s += u.r.A[row][c];
        } else {
            for (int c = k; c < cB; c += 8) s += u.r.B[row - 16][c];
        }
        s2[row][k] = s;
    }
    __syncthreads();

    // stage-2: final sums -> out[t,e]
    if (tid < 32) {
        float s = 0.f;
#pragma unroll
        for (int k = 0; k < 8; k++) s += s2[tid][k];
        const int t = (tid < 16) ? (t0A + tid) : (t0B + tid - 16);
        out[(t << 2) + e] = s;
    }
    // gamma vector (e==0 blocks cover all t across their two tiles)
    if (e == 0 && tid >= 32 && tid < 64) {
        const int j = tid - 32;
        const int t = (j < 16) ? (t0A + j) : (t0B + j - 16);
        out[4096 + t] = powf(0.999f, (float)(1023 - t));
    }
}

// ---------------------------------------------------------------------------
extern "C" void kernel_launch(void* const* d_in, const int* in_sizes, int n_in,
                              void* d_out, int out_size) {
    const float* Fx  = (const float*)d_in[0];   // [4,4,4,1024]
    const float* Dis = (const float*)d_in[1];   // [4,1024]
    const float* w0  = (const float*)d_in[2];   // [4,4,1024]
    float* out = (float*)d_out;                 // [1024*4 anti | 1024 gamma]

    k1<<<8, 256>>>(Fx, Dis, w0);
    k2<<<dim3(32, 4), 320>>>(Fx, out);
}

// round 3
// speedup vs baseline: 1.5690x; 1.2737x over previous
#include <cuda_runtime.h>
#include <math.h>

#define T      1024
#define LRC    0.01f

// Scratch (device globals — allocation is forbidden)
__device__ float g_cw[16 * T];      // control weights [rs, n]
__device__ float g_epart[32];       // 8 cluster ranks x 4 e partials

// ---------------------------------------------------------------------------
// k1 (8-CTA cluster, 256 thr/CTA): fused err + cw.
// Fires the PDL trigger immediately so k2 can start staging Fx in parallel.
// ---------------------------------------------------------------------------
__global__ void __cluster_dims__(8, 1, 1) k1(const float* __restrict__ Fx,
                                             const float* __restrict__ Dis,
                                             const float* __restrict__ w0) {
    asm volatile("griddepcontrol.launch_dependents;");

    const int tid  = threadIdx.x;
    const int rank = blockIdx.x;
    const float4* w4  = (const float4*)w0;
    const float4* fx4 = (const float4*)Fx;

    // ---- phase A: partial err dot products over this CTA's slice ----
    float acc[4] = {0.f, 0.f, 0.f, 0.f};
#pragma unroll
    for (int s = 0; s < 2; s++) {
        const int i4 = rank * 512 + s * 256 + tid;    // float4 index into w0
        const float4 w = w4[i4];
        const int rs = i4 >> 8, n4 = i4 & 255;
#pragma unroll
        for (int e = 0; e < 4; e++) {
            const float4 x = fx4[(rs << 10) + (e << 8) + n4];
            acc[e] += x.x * w.x + x.y * w.y + x.z * w.z + x.w * w.w;
        }
    }
#pragma unroll
    for (int o = 16; o; o >>= 1)
#pragma unroll
        for (int e = 0; e < 4; e++) acc[e] += __shfl_xor_sync(0xffffffffu, acc[e], o);

    __shared__ float sp[8][4];
    __shared__ float serr[4];
    if ((tid & 31) == 0)
#pragma unroll
        for (int e = 0; e < 4; e++) sp[tid >> 5][e] = acc[e];
    __syncthreads();
    if (tid < 4) {
        float s = 0.f;
#pragma unroll
        for (int wq = 0; wq < 8; wq++) s += sp[wq][tid];
        g_epart[rank * 4 + tid] = s;
    }

    asm volatile("barrier.cluster.arrive.release.aligned;" ::: "memory");
    asm volatile("barrier.cluster.wait.acquire.aligned;"   ::: "memory");

    if (tid < 4) {
        volatile const float* gp = g_epart;
        float s = 0.f;
#pragma unroll
        for (int r = 0; r < 8; r++) s += gp[r * 4 + tid];
        serr[tid] = Dis[tid * T + (T - 1)] - s;
    }
    __syncthreads();
    const float e0 = serr[0], e1 = serr[1], e2 = serr[2], e3 = serr[3];

    // ---- phase B: cw over the same slice (Fx/w0 L1-hot) ----
    float4* cw4 = (float4*)g_cw;
#pragma unroll
    for (int s = 0; s < 2; s++) {
        const int i4 = rank * 512 + s * 256 + tid;
        float4 c = w4[i4];
        const int rs = i4 >> 8, n4 = i4 & 255;
        const float4 x0 = fx4[(rs << 10) + (0 << 8) + n4];
        const float4 x1 = fx4[(rs << 10) + (1 << 8) + n4];
        const float4 x2 = fx4[(rs << 10) + (2 << 8) + n4];
        const float4 x3 = fx4[(rs << 10) + (3 << 8) + n4];
        c.x += LRC * (x0.x * e0 + x1.x * e1 + x2.x * e2 + x3.x * e3);
        c.y += LRC * (x0.y * e0 + x1.y * e1 + x2.y * e2 + x3.y * e3);
        c.z += LRC * (x0.z * e0 + x1.z * e1 + x2.z * e2 + x3.z * e3);
        c.w += LRC * (x0.w * e0 + x1.w * e1 + x2.w * e2 + x3.w * e3);
        cw4[i4] = c;
    }
}

// ---------------------------------------------------------------------------
// k2: causal correlation + output + gamma. One staging phase (132 KB dyn smem).
// grid (32 t-tile pairs, 4 e), 320 threads, 1 CTA/SM (128 CTAs = one wave).
// PDL: stages Fx first (independent of k1), then griddepcontrol.wait, then cw.
// ---------------------------------------------------------------------------
#define SFQ   1048            // sF row stride in floats (20 pad + 1024 + 4 tail)
#define NF4   262             // float4 per sF row
#define SWOFF (16 * SFQ)      // 16768: start of cw rows

extern __shared__ float smem[];

__global__ void __launch_bounds__(320, 1) k2(const float* __restrict__ Fx,
                                             float* __restrict__ out) {
    __shared__ float s2[32][8];

    const int tid = threadIdx.x;
    const int b = blockIdx.x, e = blockIdx.y;
    const int t0A = b << 4, t0B = (63 - b) << 4;
    const int cA = (t0A + 16) >> 2;                 // 4..128 chunks for tile A
    const int cB = 260 - cA;                        // chunks for tile B
    const bool active = tid < 260;
    const bool isA = tid < cA;
    const int t0 = isA ? t0A : t0B;
    const int nb = (isA ? tid : (tid - cA)) << 2;   // n-chunk base
    const int ab = 16 + t0 - nb;                    // aligned sF read base

    const float4 z4 = make_float4(0.f, 0.f, 0.f, 0.f);

    // ---- stage all 16 Fx rows (front zero-padded) — independent of k1 ----
    float4* dF = (float4*)smem;
    for (int idx = tid; idx < 16 * NF4; idx += 320) {
        const int qq = idx / NF4, i = idx - qq * NF4;
        float4 v = z4;
        if (i >= 5 && i < 261)
            v = ((const float4*)(Fx + (((qq << 2) + e) << 10)))[i - 5];
        dF[qq * NF4 + i] = v;
    }

    // ---- wait for k1's g_cw to be visible, then stage cw ----
    asm volatile("griddepcontrol.wait;" ::: "memory");
    float4* dW = (float4*)(smem + SWOFF);
    const float4* ws = (const float4*)g_cw;
    for (int idx = tid; idx < 16 * 256; idx += 320)
        dW[idx] = ws[idx];
    __syncthreads();

    // ---- compute: 16 t-accumulators per thread, 16 rs fully in smem ----
    float acc[16];
#pragma unroll
    for (int j = 0; j < 16; j++) acc[j] = 0.f;

    if (active) {
#pragma unroll 4
        for (int qq = 0; qq < 16; qq++) {
            const float4 w = *(const float4*)&smem[SWOFF + (qq << 10) + nb];
            const float4* F4 = (const float4*)&smem[qq * SFQ + ab];
            float ff[24];
#pragma unroll
            for (int m = 0; m < 6; m++) {
                const float4 v = F4[m];
                ff[4 * m + 0] = v.x; ff[4 * m + 1] = v.y;
                ff[4 * m + 2] = v.z; ff[4 * m + 3] = v.w;
            }
#pragma unroll
            for (int j = 0; j < 16; j++)
                acc[j] += ff[4 + j] * w.x + ff[3 + j] * w.y
                        + ff[2 + j] * w.z + ff[1 + j] * w.w;
        }
    }
    __syncthreads();

    // ---- per-chunk partials overlay the staging buffer ----
    float* redA = smem;                 // [16][128]
    float* redB = smem + 16 * 128;      // [16][256]
    if (active) {
        if (isA) {
#pragma unroll
            for (int j = 0; j < 16; j++) redA[j * 128 + tid] = acc[j];
        } else {
#pragma unroll
            for (int j = 0; j < 16; j++) redB[j * 256 + (tid - cA)] = acc[j];
        }
    }
    __syncthreads();

    // ---- stage-1 reduction: 8 partials per (tile,t) row ----
    if (tid < 256) {
        const int row = tid >> 3, k = tid & 7;
        float s = 0.f;
        if (row < 16) {
            for (int c = k; c < cA; c += 8) s += redA[row * 128 + c];
        } else {
            for (int c = k; c < cB; c += 8) s += redB[(row - 16) * 256 + c];
        }
        s2[row][k] = s;
    }
    __syncthreads();

    // ---- stage-2: final sums -> out[t,e] ----
    if (tid < 32) {
        float s = 0.f;
#pragma unroll
        for (int k = 0; k < 8; k++) s += s2[tid][k];
        const int t = (tid < 16) ? (t0A + tid) : (t0B + tid - 16);
        out[(t << 2) + e] = s;
    }
    // gamma vector (e==0 blocks cover all t across their two tiles)
    if (e == 0 && tid >= 32 && tid < 64) {
        const int j = tid - 32;
        const int t = (j < 16) ? (t0A + j) : (t0B + j - 16);
        out[4096 + t] = powf(0.999f, (float)(1023 - t));
    }
}

// ---------------------------------------------------------------------------
extern "C" void kernel_launch(void* const* d_in, const int* in_sizes, int n_in,
                              void* d_out, int out_size) {
    const float* Fx  = (const float*)d_in[0];   // [4,4,4,1024]
    const float* Dis = (const float*)d_in[1];   // [4,1024]
    const float* w0  = (const float*)d_in[2];   // [4,4,1024]
    float* out = (float*)d_out;                 // [1024*4 anti | 1024 gamma]

    const size_t dynBytes = (size_t)(SWOFF + 16 * 1024) * sizeof(float); // 132,608
    cudaFuncSetAttribute(k2, cudaFuncAttributeMaxDynamicSharedMemorySize,
                         (int)dynBytes);

    k1<<<8, 256>>>(Fx, Dis, w0);

    // k2 with programmatic dependent launch (overlaps with k1)
    cudaLaunchConfig_t cfg = {};
    cfg.gridDim = dim3(32, 4);
    cfg.blockDim = dim3(320);
    cfg.dynamicSmemBytes = dynBytes;
    cfg.stream = 0;
    cudaLaunchAttribute attr[1];
    attr[0].id = cudaLaunchAttributeProgrammaticStreamSerialization;
    attr[0].val.programmaticStreamSerializationAllowed = 1;
    cfg.attrs = attr;
    cfg.numAttrs = 1;
    cudaLaunchKernelEx(&cfg, k2, Fx, out);
}

// round 5
// speedup vs baseline: 1.7887x; 1.1400x over previous
#include <cuda_runtime.h>
#include <cstdint>
#include <math.h>

#define T      1024
#define LRC    0.01f

// Scratch (device globals — allocation is forbidden)
__device__ float g_cw[16 * T];      // control weights [rs, n]
__device__ float g_epart[32];       // 8 cluster ranks x 4 e partials

// ---------------------------------------------------------------------------
// k1 (8-CTA cluster, 256 thr/CTA): fused err + cw.
// Fires the PDL trigger immediately so k2 can start staging Fx in parallel.
// ---------------------------------------------------------------------------
__global__ void __cluster_dims__(8, 1, 1) k1(const float* __restrict__ Fx,
                                             const float* __restrict__ Dis,
                                             const float* __restrict__ w0) {
    asm volatile("griddepcontrol.launch_dependents;");

    const int tid  = threadIdx.x;
    const int rank = blockIdx.x;
    const float4* w4  = (const float4*)w0;
    const float4* fx4 = (const float4*)Fx;

    // ---- phase A: partial err dot products over this CTA's slice ----
    float acc[4] = {0.f, 0.f, 0.f, 0.f};
#pragma unroll
    for (int s = 0; s < 2; s++) {
        const int i4 = rank * 512 + s * 256 + tid;    // float4 index into w0
        const float4 w = w4[i4];
        const int rs = i4 >> 8, n4 = i4 & 255;
#pragma unroll
        for (int e = 0; e < 4; e++) {
            const float4 x = fx4[(rs << 10) + (e << 8) + n4];
            acc[e] += x.x * w.x + x.y * w.y + x.z * w.z + x.w * w.w;
        }
    }
#pragma unroll
    for (int o = 16; o; o >>= 1)
#pragma unroll
        for (int e = 0; e < 4; e++) acc[e] += __shfl_xor_sync(0xffffffffu, acc[e], o);

    __shared__ float sp[8][4];
    __shared__ float serr[4];
    if ((tid & 31) == 0)
#pragma unroll
        for (int e = 0; e < 4; e++) sp[tid >> 5][e] = acc[e];
    __syncthreads();
    if (tid < 4) {
        float s = 0.f;
#pragma unroll
        for (int wq = 0; wq < 8; wq++) s += sp[wq][tid];
        g_epart[rank * 4 + tid] = s;
    }

    asm volatile("barrier.cluster.arrive.release.aligned;" ::: "memory");
    asm volatile("barrier.cluster.wait.acquire.aligned;"   ::: "memory");

    if (tid < 4) {
        volatile const float* gp = g_epart;
        float s = 0.f;
#pragma unroll
        for (int r = 0; r < 8; r++) s += gp[r * 4 + tid];
        serr[tid] = Dis[tid * T + (T - 1)] - s;
    }
    __syncthreads();
    const float e0 = serr[0], e1 = serr[1], e2 = serr[2], e3 = serr[3];

    // ---- phase B: cw over the same slice (Fx/w0 L1-hot) ----
    float4* cw4 = (float4*)g_cw;
#pragma unroll
    for (int s = 0; s < 2; s++) {
        const int i4 = rank * 512 + s * 256 + tid;
        float4 c = w4[i4];
        const int rs = i4 >> 8, n4 = i4 & 255;
        const float4 x0 = fx4[(rs << 10) + (0 << 8) + n4];
        const float4 x1 = fx4[(rs << 10) + (1 << 8) + n4];
        const float4 x2 = fx4[(rs << 10) + (2 << 8) + n4];
        const float4 x3 = fx4[(rs << 10) + (3 << 8) + n4];
        c.x += LRC * (x0.x * e0 + x1.x * e1 + x2.x * e2 + x3.x * e3);
        c.y += LRC * (x0.y * e0 + x1.y * e1 + x2.y * e2 + x3.y * e3);
        c.z += LRC * (x0.z * e0 + x1.z * e1 + x2.z * e2 + x3.z * e3);
        c.w += LRC * (x0.w * e0 + x1.w * e1 + x2.w * e2 + x3.w * e3);
        cw4[i4] = c;
    }
}

// ---------------------------------------------------------------------------
// k2: causal correlation + output + gamma.
// grid (32 pair-tiles, 4 e, 2 rs-halves), cluster (1,1,2), 320 thr, 66 KB smem
// -> 2 CTAs/SM = 20 warps/SM (vs 10 before): double latency hiding, same
// per-SM work. Each CTA computes its 8-rs partial; rank1 pushes 32 floats to
// rank0 via DSMEM; rank0 combines deterministically and writes out.
// PDL: Fx staging (k1-independent) precedes griddepcontrol.wait; cw after.
// ---------------------------------------------------------------------------
#define SFQ   1048            // sF row stride in floats (20 pad + 1024 + 4 tail)
#define NF4   262             // float4 per sF row
#define SWOFF (8 * SFQ)       // 8384: start of cw rows (8 rows of 1024)

extern __shared__ float smem[];

__global__ void __launch_bounds__(320, 2) __cluster_dims__(1, 1, 2)
k2(const float* __restrict__ Fx, float* __restrict__ out) {
    __shared__ float s2[32][8];
    __shared__ float sXfer[32];

    const int tid  = threadIdx.x;
    const int b    = blockIdx.x;
    const int e    = blockIdx.y;
    const int half = blockIdx.z;                    // rs-half = cluster rank
    const int t0A = b << 4, t0B = (63 - b) << 4;
    const int cA = (t0A + 16) >> 2;                 // 4..128 chunks for tile A
    const int cB = 260 - cA;                        // chunks for tile B
    const bool active = tid < 260;
    const bool isA = tid < cA;
    const int t0 = isA ? t0A : t0B;
    const int nb = (isA ? tid : (tid - cA)) << 2;   // n-chunk base
    const int ab = 16 + t0 - nb;                    // aligned sF read base

    const float4 z4 = make_float4(0.f, 0.f, 0.f, 0.f);

    // ---- stage this half's 8 Fx rows (front zero-padded) — k1-independent ----
    float4* dF = (float4*)smem;
    for (int idx = tid; idx < 8 * NF4; idx += 320) {
        const int qq = idx / NF4, i = idx - qq * NF4;
        const int rs = (half << 3) + qq;
        float4 v = z4;
        if (i >= 5 && i < 261)
            v = ((const float4*)(Fx + (((rs << 2) + e) << 10)))[i - 5];
        dF[qq * NF4 + i] = v;
    }

    // ---- wait for k1's g_cw, then stage this half's 8 cw rows ----
    asm volatile("griddepcontrol.wait;" ::: "memory");
    float4* dW = (float4*)(smem + SWOFF);
    const float4* ws = (const float4*)(g_cw + (half << 3 << 10));
    for (int idx = tid; idx < 8 * 256; idx += 320)
        dW[idx] = ws[idx];
    __syncthreads();

    // ---- compute: 16 t-accumulators per thread over 8 rs rows ----
    float acc[16];
#pragma unroll
    for (int j = 0; j < 16; j++) acc[j] = 0.f;

    if (active) {
#pragma unroll
        for (int qq = 0; qq < 8; qq++) {
            const float4 w = *(const float4*)&smem[SWOFF + (qq << 10) + nb];
            const float4* F4 = (const float4*)&smem[qq * SFQ + ab];
            float ff[24];
#pragma unroll
            for (int m = 0; m < 6; m++) {
                const float4 v = F4[m];
                ff[4 * m + 0] = v.x; ff[4 * m + 1] = v.y;
                ff[4 * m + 2] = v.z; ff[4 * m + 3] = v.w;
            }
#pragma unroll
            for (int j = 0; j < 16; j++)
                acc[j] += ff[4 + j] * w.x + ff[3 + j] * w.y
                        + ff[2 + j] * w.z + ff[1 + j] * w.w;
        }
    }
    __syncthreads();

    // ---- per-chunk partials overlay the staging buffer ----
    float* redA = smem;                 // [16][128]
    float* redB = smem + 16 * 128;      // [16][256]
    if (active) {
        if (isA) {
#pragma unroll
            for (int j = 0; j < 16; j++) redA[j * 128 + tid] = acc[j];
        } else {
#pragma unroll
            for (int j = 0; j < 16; j++) redB[j * 256 + (tid - cA)] = acc[j];
        }
    }
    __syncthreads();

    // ---- stage-1 reduction: 8 partials per (tile,t) row ----
    if (tid < 256) {
        const int row = tid >> 3, k = tid & 7;
        float s = 0.f;
        if (row < 16) {
            for (int c = k; c < cA; c += 8) s += redA[row * 128 + c];
        } else {
            for (int c = k; c < cB; c += 8) s += redB[(row - 16) * 256 + c];
        }
        s2[row][k] = s;
    }
    __syncthreads();

    // ---- stage-2: this half's 32 sums; rank1 ships them to rank0 ----
    float s = 0.f;
    if (tid < 32) {
#pragma unroll
        for (int k = 0; k < 8; k++) s += s2[tid][k];
        if (half == 1) {
            unsigned int local =
                (unsigned int)__cvta_generic_to_shared(&sXfer[tid]);
            unsigned int remote;
            asm("mapa.shared::cluster.u32 %0, %1, %2;"
                : "=r"(remote) : "r"(local), "r"(0));
            asm volatile("st.shared::cluster.f32 [%0], %1;"
                         :: "r"(remote), "f"(s) : "memory");
        }
    }
    // gamma vector (half==0, e==0 blocks cover all t across their two tiles)
    if (half == 0 && e == 0 && tid >= 32 && tid < 64) {
        const int j = tid - 32;
        const int t = (j < 16) ? (t0A + j) : (t0B + j - 16);
        out[4096 + t] = powf(0.999f, (float)(1023 - t));
    }

    asm volatile("barrier.cluster.arrive.release.aligned;" ::: "memory");
    asm volatile("barrier.cluster.wait.acquire.aligned;"   ::: "memory");

    if (half == 0 && tid < 32) {
        const int t = (tid < 16) ? (t0A + tid) : (t0B + tid - 16);
        out[(t << 2) + e] = s + sXfer[tid];
    }
}

// ---------------------------------------------------------------------------
extern "C" void kernel_launch(void* const* d_in, const int* in_sizes, int n_in,
                              void* d_out, int out_size) {
    const float* Fx  = (const float*)d_in[0];   // [4,4,4,1024]
    const float* Dis = (const float*)d_in[1];   // [4,1024]
    const float* w0  = (const float*)d_in[2];   // [4,4,1024]
    float* out = (float*)d_out;                 // [1024*4 anti | 1024 gamma]

    const size_t dynBytes = (size_t)(SWOFF + 8 * 1024) * sizeof(float); // 66,304
    cudaFuncSetAttribute(k2, cudaFuncAttributeMaxDynamicSharedMemorySize,
                         (int)dynBytes);

    k1<<<8, 256>>>(Fx, Dis, w0);

    // k2 with programmatic dependent launch (overlaps with k1)
    cudaLaunchConfig_t cfg = {};
    cfg.gridDim = dim3(32, 4, 2);
    cfg.blockDim = dim3(320);
    cfg.dynamicSmemBytes = dynBytes;
    cfg.stream = 0;
    cudaLaunchAttribute attr[1];
    attr[0].id = cudaLaunchAttributeProgrammaticStreamSerialization;
    attr[0].val.programmaticStreamSerializationAllowed = 1;
    cfg.attrs = attr;
    cfg.numAttrs = 1;
    cudaLaunchKernelEx(&cfg, k2, Fx, out);
}